// round 1
// baseline (speedup 1.0000x reference)
#include <cuda_runtime.h>
#include <math.h>

#define NN   100000
#define NE   500000
#define FEAT 128
#define HID  256
#define NL   16384

// ---------------- scratch (no allocations allowed) ----------------
__device__ float g_h0[NN * HID];      // h0, later reused for h2
__device__ float g_h1[NN * HID];      // h1
__device__ float g_agg[NN * HID];     // nbsum -> mean
__device__ float g_deg[NN];
__device__ float g_comb[NL * 4 * HID];
__device__ float g_hid[NL * HID];
__device__ int   g_is64;

// ---------------- index dtype detection ----------------
// If indices are int64 (values < 2^31), every odd 32-bit word of the buffer is 0.
// For int32 random indices in [0,1e5) that is impossible over 256 samples.
__global__ void detect_kernel(const int* __restrict__ words) {
    __shared__ int nz;
    if (threadIdx.x == 0) nz = 0;
    __syncthreads();
    if (words[threadIdx.x * 2 + 1] != 0) atomicExch(&nz, 1);
    __syncthreads();
    if (threadIdx.x == 0) g_is64 = (nz == 0) ? 1 : 0;
}

__device__ __forceinline__ long long getIdx(const void* p, long long i) {
    if (g_is64) return ((const long long*)p)[i];
    return (long long)((const int*)p)[i];
}

// ---------------- zero ----------------
__global__ void zero_kernel(float* __restrict__ p, int n) {
    int i = blockIdx.x * blockDim.x + threadIdx.x;
    int stride = gridDim.x * blockDim.x;
    for (; i < n; i += stride) p[i] = 0.0f;
}

// ---------------- degree ----------------
__global__ void deg_kernel(const void* __restrict__ ei, float* __restrict__ deg) {
    int e = blockIdx.x * blockDim.x + threadIdx.x;
    if (e < NE) {
        long long dst = getIdx(ei, (long long)NE + e);
        atomicAdd(&deg[dst], 1.0f);
    }
}

// ---------------- scatter: agg[dst] += h[src], warp per edge ----------------
__global__ void scatter_kernel(const void* __restrict__ ei,
                               const float* __restrict__ h,
                               float* __restrict__ agg) {
    int gtid = blockIdx.x * blockDim.x + threadIdx.x;
    int w = gtid >> 5;
    int lane = gtid & 31;
    if (w >= NE) return;
    long long src = getIdx(ei, w);
    long long dst = getIdx(ei, (long long)NE + w);
    const float* hs = h + src * HID;
    float* ad = agg + dst * HID;
#pragma unroll
    for (int j = 0; j < HID / 32; ++j) {
        int c = lane + j * 32;
        atomicAdd(&ad[c], hs[c]);
    }
}

// ---------------- mean: agg = (agg + h) / (deg + 1), float4 ----------------
__global__ void mean_kernel(float* __restrict__ agg,
                            const float* __restrict__ h,
                            const float* __restrict__ deg) {
    int i = blockIdx.x * blockDim.x + threadIdx.x;                 // float4 index
    int total = NN * (HID / 4);
    int stride = gridDim.x * blockDim.x;
    for (; i < total; i += stride) {
        int n = i / (HID / 4);
        float inv = 1.0f / (deg[n] + 1.0f);
        float4 a = ((const float4*)agg)[i];
        float4 hv = ((const float4*)h)[i];
        a.x = (a.x + hv.x) * inv;
        a.y = (a.y + hv.y) * inv;
        a.z = (a.z + hv.z) * inv;
        a.w = (a.w + hv.w) * inv;
        ((float4*)agg)[i] = a;
    }
}

// ---------------- generic GEMM: C = act(A1@W1^T + A2@W2^T + bias) ----------------
// A1: [M,K1] row-major, W1: [N,K1] row-major. A2/W2 optional (K2 may be 0).
// BM=128, BN=64, BK=16, 256 threads, 8x4 per thread.
__global__ __launch_bounds__(256)
void gemm_bias_act(const float* __restrict__ A1, int K1,
                   const float* __restrict__ A2, int K2,
                   const float* __restrict__ W1,
                   const float* __restrict__ W2,
                   const float* __restrict__ bias,
                   float* __restrict__ C, int M, int N, int doRelu) {
    constexpr int BM = 128, BN = 64, BK = 16;
    constexpr int BMp = 132, BNp = 68;
    __shared__ float As[BK * BMp];
    __shared__ float Bs[BK * BNp];

    int tid = threadIdx.x;
    int tx = tid & 15;        // 0..15 -> 4 cols each
    int ty = tid >> 4;        // 0..15 -> 8 rows each
    int row0 = blockIdx.x * BM;
    int col0 = blockIdx.y * BN;

    float acc[8][4];
#pragma unroll
    for (int i = 0; i < 8; ++i)
#pragma unroll
        for (int j = 0; j < 4; ++j) acc[i][j] = 0.0f;

    int t1 = K1 / BK;
    int tTot = t1 + K2 / BK;

    for (int tk = 0; tk < tTot; ++tk) {
        const float* A;
        const float* W;
        int K, kk;
        if (tk < t1) { A = A1; W = W1; K = K1; kk = tk * BK; }
        else         { A = A2; W = W2; K = K2; kk = (tk - t1) * BK; }

        // load A tile: 2 float4 per thread, store transposed As[k][m]
#pragma unroll
        for (int hld = 0; hld < 2; ++hld) {
            int f = tid + hld * 256;        // 0..511 float4 slots
            int r = f >> 2;                  // row in tile 0..127
            int kq = f & 3;                  // which float4 along K
            float4 v = make_float4(0.f, 0.f, 0.f, 0.f);
            int grow = row0 + r;
            if (grow < M)
                v = *(const float4*)(A + (long long)grow * K + kk + kq * 4);
            As[(kq * 4 + 0) * BMp + r] = v.x;
            As[(kq * 4 + 1) * BMp + r] = v.y;
            As[(kq * 4 + 2) * BMp + r] = v.z;
            As[(kq * 4 + 3) * BMp + r] = v.w;
        }
        // load B tile: Bs[k][n] = W[col0+n][kk+k]; 1 float4 per thread
        {
            int n = tid >> 2;
            int kq = tid & 3;
            float4 v = *(const float4*)(W + (long long)(col0 + n) * K + kk + kq * 4);
            Bs[(kq * 4 + 0) * BNp + n] = v.x;
            Bs[(kq * 4 + 1) * BNp + n] = v.y;
            Bs[(kq * 4 + 2) * BNp + n] = v.z;
            Bs[(kq * 4 + 3) * BNp + n] = v.w;
        }
        __syncthreads();

#pragma unroll
        for (int k = 0; k < BK; ++k) {
            float4 a0 = *(const float4*)&As[k * BMp + ty * 8];
            float4 a1 = *(const float4*)&As[k * BMp + ty * 8 + 4];
            float4 b  = *(const float4*)&Bs[k * BNp + tx * 4];
            float am[8] = {a0.x, a0.y, a0.z, a0.w, a1.x, a1.y, a1.z, a1.w};
            float bn[4] = {b.x, b.y, b.z, b.w};
#pragma unroll
            for (int i = 0; i < 8; ++i)
#pragma unroll
                for (int j = 0; j < 4; ++j)
                    acc[i][j] = fmaf(am[i], bn[j], acc[i][j]);
        }
        __syncthreads();
    }

    float4 bb = *(const float4*)(bias + col0 + tx * 4);
    float bv[4] = {bb.x, bb.y, bb.z, bb.w};
#pragma unroll
    for (int i = 0; i < 8; ++i) {
        int row = row0 + ty * 8 + i;
        if (row >= M) break;
        float4 o;
        float v0 = acc[i][0] + bv[0];
        float v1 = acc[i][1] + bv[1];
        float v2 = acc[i][2] + bv[2];
        float v3 = acc[i][3] + bv[3];
        if (doRelu) {
            v0 = fmaxf(v0, 0.f); v1 = fmaxf(v1, 0.f);
            v2 = fmaxf(v2, 0.f); v3 = fmaxf(v3, 0.f);
        }
        o.x = v0; o.y = v1; o.z = v2; o.w = v3;
        *(float4*)(C + (long long)row * N + col0 + tx * 4) = o;
    }
}

// ---------------- link feature gather ----------------
__global__ void gather_kernel(const void* __restrict__ srcI,
                              const void* __restrict__ dstI,
                              const float* __restrict__ h2,
                              float* __restrict__ comb) {
    int t = blockIdx.x * blockDim.x + threadIdx.x;
    if (t >= NL * HID) return;
    int l = t >> 8;
    int k = t & 255;
    long long s_n = getIdx(srcI, l);
    long long d_n = getIdx(dstI, l);
    float s = h2[s_n * HID + k];
    float d = h2[d_n * HID + k];
    float* c = comb + (long long)l * (4 * HID);
    c[k] = s;
    c[HID + k] = d;
    c[2 * HID + k] = s * d;
    c[3 * HID + k] = fabsf(s - d);
}

// ---------------- final: sigmoid(hidden . wp2 + b), warp per link ----------------
__global__ void final_kernel(const float* __restrict__ hid,
                             const float* __restrict__ wp2,
                             const float* __restrict__ bp2,
                             float* __restrict__ out) {
    int gtid = blockIdx.x * blockDim.x + threadIdx.x;
    int w = gtid >> 5;
    int lane = gtid & 31;
    if (w >= NL) return;
    const float* h = hid + (long long)w * HID;
    float s = 0.f;
#pragma unroll
    for (int j = 0; j < HID / 32; ++j) {
        int c = lane + j * 32;
        s = fmaf(h[c], wp2[c], s);
    }
#pragma unroll
    for (int o = 16; o > 0; o >>= 1)
        s += __shfl_down_sync(0xffffffffu, s, o);
    if (lane == 0) {
        float logit = s + bp2[0];
        out[w] = 1.0f / (1.0f + expf(-logit));
    }
}

// ---------------- launcher ----------------
extern "C" void kernel_launch(void* const* d_in, const int* in_sizes, int n_in,
                              void* d_out, int out_size) {
    const float* x     = (const float*)d_in[0];
    const void*  ei    = d_in[1];
    const void*  srcI  = d_in[3];
    const void*  dstI  = d_in[4];
    const float* w_emb = (const float*)d_in[5];
    const float* b_emb = (const float*)d_in[6];
    const float* wl0   = (const float*)d_in[8];
    const float* bl0   = (const float*)d_in[9];
    const float* wr0   = (const float*)d_in[10];
    const float* wl1   = (const float*)d_in[13];
    const float* bl1   = (const float*)d_in[14];
    const float* wr1   = (const float*)d_in[15];
    const float* wp1   = (const float*)d_in[18];
    const float* bp1   = (const float*)d_in[19];
    const float* wp2   = (const float*)d_in[20];
    const float* bp2   = (const float*)d_in[21];
    float* out = (float*)d_out;

    float *h0, *h1, *agg, *deg, *comb, *hid;
    cudaGetSymbolAddress((void**)&h0,   g_h0);
    cudaGetSymbolAddress((void**)&h1,   g_h1);
    cudaGetSymbolAddress((void**)&agg,  g_agg);
    cudaGetSymbolAddress((void**)&deg,  g_deg);
    cudaGetSymbolAddress((void**)&comb, g_comb);
    cudaGetSymbolAddress((void**)&hid,  g_hid);

    const int ZB = 2048;
    dim3 gemmGridN((NN + 127) / 128, HID / 64);   // (782, 4)
    dim3 gemmGridL((NL + 127) / 128, HID / 64);   // (128, 4)

    // 0. detect index width
    detect_kernel<<<1, 256>>>((const int*)ei);

    // 1. zero deg + agg; degree
    zero_kernel<<<(NN + 255) / 256, 256>>>(deg, NN);
    zero_kernel<<<ZB, 256>>>(agg, NN * HID);
    deg_kernel<<<(NE + 255) / 256, 256>>>(ei, deg);

    // 2. embedding: h0 = x @ w_emb^T + b_emb
    gemm_bias_act<<<gemmGridN, 256>>>(x, FEAT, nullptr, 0, w_emb, nullptr,
                                      b_emb, h0, NN, HID, 0);

    // 3. layer 0
    scatter_kernel<<<(NE * 32 + 255) / 256, 256>>>(ei, h0, agg);
    mean_kernel<<<25000, 256>>>(agg, h0, deg);
    gemm_bias_act<<<gemmGridN, 256>>>(agg, HID, h0, HID, wl0, wr0,
                                      bl0, h1, NN, HID, 1);

    // 4. layer 1 (h2 written into h0 buffer)
    zero_kernel<<<ZB, 256>>>(agg, NN * HID);
    scatter_kernel<<<(NE * 32 + 255) / 256, 256>>>(ei, h1, agg);
    mean_kernel<<<25000, 256>>>(agg, h1, deg);
    gemm_bias_act<<<gemmGridN, 256>>>(agg, HID, h1, HID, wl1, wr1,
                                      bl1, h0, NN, HID, 1);

    // 5. link head
    gather_kernel<<<(NL * HID + 255) / 256, 256>>>(srcI, dstI, h0, comb);
    gemm_bias_act<<<gemmGridL, 256>>>(comb, 4 * HID, nullptr, 0, wp1, nullptr,
                                      bp1, hid, NL, HID, 1);
    final_kernel<<<(NL * 32 + 255) / 256, 256>>>(hid, wp2, bp2, out);
}

// round 4
// speedup vs baseline: 1.2634x; 1.2634x over previous
#include <cuda_runtime.h>
#include <cuda_bf16.h>
#include <cstdint>
#include <math.h>

#define NN   100000
#define NE   500000
#define FEAT 128
#define HID  256
#define NL   16384

// ---------------- scratch (no allocations allowed) ----------------
__device__ float g_h0[NN * HID];      // h0, later reused for h2
__device__ float g_h1[NN * HID];      // h1
__device__ float g_agg[NN * HID];     // nbsum (mean fused into GEMM loader)
__device__ float g_deg[NN];
__device__ float g_comb[NL * 4 * HID];
__device__ float g_hid[NL * HID];
__device__ int   g_is64;

// ---------------- helpers ----------------
__device__ __forceinline__ uint32_t smem_u32(const void* p) {
    uint32_t a;
    asm("{ .reg .u64 t; cvta.to.shared.u64 t, %1; cvt.u32.u64 %0, t; }" : "=r"(a) : "l"(p));
    return a;
}

#define LDSM_X4(r0, r1, r2, r3, addr) \
    asm volatile("ldmatrix.sync.aligned.m8n8.x4.shared.b16 {%0,%1,%2,%3}, [%4];" \
                 : "=r"(r0), "=r"(r1), "=r"(r2), "=r"(r3) : "r"(addr))

__device__ __forceinline__ void mma_bf16(float* d, const uint32_t* a,
                                         uint32_t b0, uint32_t b1) {
    asm volatile(
        "mma.sync.aligned.m16n8k16.row.col.f32.bf16.bf16.f32 "
        "{%0,%1,%2,%3}, {%4,%5,%6,%7}, {%8,%9}, {%0,%1,%2,%3};"
        : "+f"(d[0]), "+f"(d[1]), "+f"(d[2]), "+f"(d[3])
        : "r"(a[0]), "r"(a[1]), "r"(a[2]), "r"(a[3]), "r"(b0), "r"(b1));
}

// split fp32 pair -> packed bf16x2 hi and lo
__device__ __forceinline__ void split2(float x, float y, uint32_t& hi, uint32_t& lo) {
    __nv_bfloat16 hx = __float2bfloat16_rn(x);
    __nv_bfloat16 hy = __float2bfloat16_rn(y);
    float rx = x - __bfloat162float(hx);
    float ry = y - __bfloat162float(hy);
    __nv_bfloat16 lx = __float2bfloat16_rn(rx);
    __nv_bfloat16 ly = __float2bfloat16_rn(ry);
    hi = (uint32_t)__bfloat16_as_ushort(hx) | ((uint32_t)__bfloat16_as_ushort(hy) << 16);
    lo = (uint32_t)__bfloat16_as_ushort(lx) | ((uint32_t)__bfloat16_as_ushort(ly) << 16);
}

// ---------------- index dtype detection ----------------
__global__ void detect_kernel(const int* __restrict__ words) {
    __shared__ int nz;
    if (threadIdx.x == 0) nz = 0;
    __syncthreads();
    if (words[threadIdx.x * 2 + 1] != 0) atomicExch(&nz, 1);
    __syncthreads();
    if (threadIdx.x == 0) g_is64 = (nz == 0) ? 1 : 0;
}
__device__ __forceinline__ long long getIdx(const void* p, long long i) {
    if (g_is64) return ((const long long*)p)[i];
    return (long long)((const int*)p)[i];
}

// ---------------- degree ----------------
__global__ void deg_kernel(const void* __restrict__ ei, float* __restrict__ deg) {
    int e = blockIdx.x * blockDim.x + threadIdx.x;
    if (e < NE) {
        long long dst = getIdx(ei, (long long)NE + e);
        atomicAdd(&deg[dst], 1.0f);
    }
}

// ---------------- scatter: agg[dst] += h[src], warp/edge, vec4 red ----------------
__global__ void scatter_kernel(const void* __restrict__ ei,
                               const float* __restrict__ h,
                               float* __restrict__ agg) {
    int gtid = blockIdx.x * blockDim.x + threadIdx.x;
    int w = gtid >> 5;
    int lane = gtid & 31;
    if (w >= NE) return;
    long long src = getIdx(ei, w);
    long long dst = getIdx(ei, (long long)NE + w);
    const float4* hs = (const float4*)(h + src * HID);
    float4* ad = (float4*)(agg + dst * HID);
#pragma unroll
    for (int j = 0; j < 2; ++j) {
        float4 v = __ldg(hs + lane + j * 32);
        asm volatile("red.global.add.v4.f32 [%0], {%1, %2, %3, %4};"
                     :: "l"(ad + lane + j * 32), "f"(v.x), "f"(v.y), "f"(v.z), "f"(v.w)
                     : "memory");
    }
}

// ---------------- HMMA bf16-split GEMM ----------------
// C[M,256] = act( [A1'(mean-fused) | A2] @ [W1 | W2]^T + bias )
// CTA tile 128(M) x 128(N), K chunk = 32 fp32, double-buffered SMEM,
// 3 accumulation passes (hi*hi, hi*lo, lo*hi).
#define KC     32
#define STRIDE 40            // bf16 elements per SMEM row (32 used + 8 pad)
#define ROWB   (STRIDE * 2)  // 80 bytes
#define ASZ    (128 * ROWB)  // 10240 bytes per matrix variant
#define AHI    0
#define ALO    ASZ
#define BHI    (2 * ASZ)
#define BLO    (3 * ASZ)
#define STAGE  (4 * ASZ)     // 40960
#define GEMM_SMEM (2 * STAGE)

__global__ __launch_bounds__(256, 1)
void gemm_mma(const float* __restrict__ A1, int K1,
              const float* __restrict__ addA, const float* __restrict__ degp,
              const float* __restrict__ A2, int K2,
              const float* __restrict__ W1, const float* __restrict__ W2,
              const float* __restrict__ bias,
              float* __restrict__ C, int M, int doRelu) {
    extern __shared__ char smem[];
    const uint32_t sbase = smem_u32(smem);
    const int tid = threadIdx.x;
    const int lane = tid & 31;
    const int wid = tid >> 5;
    const int wm = wid & 3;          // 4 warps along M
    const int wn = wid >> 2;         // 2 warps along N
    const int m0w = wm * 32;
    const int n0w = wn * 64;
    const int row0 = blockIdx.x * 128;
    const int n0 = blockIdx.y * 128;

    float acc[2][8][4];
#pragma unroll
    for (int t = 0; t < 2; ++t)
#pragma unroll
        for (int n = 0; n < 8; ++n)
#pragma unroll
            for (int j = 0; j < 4; ++j) acc[t][n][j] = 0.0f;

    const int nch1 = K1 / KC;
    const int nch = nch1 + K2 / KC;

    float4 vA[4], vB[4];

    // -------- prefetch chunk c into registers --------
    auto prefetch = [&](int c) {
        const float* A; const float* W; const float* Add; int K, kk;
        if (c < nch1) { A = A1; W = W1; Add = addA; K = K1; kk = c * KC; }
        else          { A = A2; W = W2; Add = nullptr; K = K2; kk = (c - nch1) * KC; }
#pragma unroll
        for (int i = 0; i < 4; ++i) {
            int idx = tid + i * 256;
            int r = idx >> 3, q = idx & 7;
            int grow = row0 + r;
            float4 v = make_float4(0.f, 0.f, 0.f, 0.f);
            if (grow < M) {
                v = __ldg((const float4*)(A + (size_t)grow * K + kk + q * 4));
                if (Add) {
                    float4 w = __ldg((const float4*)(Add + (size_t)grow * K + kk + q * 4));
                    float inv = 1.0f / (__ldg(degp + grow) + 1.0f);
                    v.x = (v.x + w.x) * inv; v.y = (v.y + w.y) * inv;
                    v.z = (v.z + w.z) * inv; v.w = (v.w + w.w) * inv;
                }
            }
            vA[i] = v;
            vB[i] = __ldg((const float4*)(W + (size_t)(n0 + r) * K + kk + q * 4));
        }
    };

    // -------- convert + store registers into SMEM stage --------
    auto store_stage = [&](int stg) {
        uint32_t sb = sbase + stg * STAGE;
#pragma unroll
        for (int i = 0; i < 4; ++i) {
            int idx = tid + i * 256;
            int r = idx >> 3, q = idx & 7;
            uint32_t off = (uint32_t)(r * ROWB + q * 8);
            uint32_t h01, l01, h23, l23;
            split2(vA[i].x, vA[i].y, h01, l01);
            split2(vA[i].z, vA[i].w, h23, l23);
            asm volatile("st.shared.v2.b32 [%0], {%1, %2};" :: "r"(sb + AHI + off), "r"(h01), "r"(h23) : "memory");
            asm volatile("st.shared.v2.b32 [%0], {%1, %2};" :: "r"(sb + ALO + off), "r"(l01), "r"(l23) : "memory");
            split2(vB[i].x, vB[i].y, h01, l01);
            split2(vB[i].z, vB[i].w, h23, l23);
            asm volatile("st.shared.v2.b32 [%0], {%1, %2};" :: "r"(sb + BHI + off), "r"(h01), "r"(h23) : "memory");
            asm volatile("st.shared.v2.b32 [%0], {%1, %2};" :: "r"(sb + BLO + off), "r"(l01), "r"(l23) : "memory");
        }
    };

    // ldmatrix lane offsets (bytes)
    const uint32_t aRow = (uint32_t)((m0w + (lane & 15)) * ROWB + ((lane >> 4) * 8) * 2);
    const int nb = (lane < 16) ? (lane & 7) : (8 + (lane & 7));
    const uint32_t bRow = (uint32_t)((n0w + nb) * ROWB + (((lane >> 3) & 1) * 8) * 2);

    // -------- mma over one stage --------
    auto compute = [&](int stg) {
        uint32_t sb = sbase + stg * STAGE;
#pragma unroll
        for (int ks = 0; ks < 2; ++ks) {
#pragma unroll
            for (int p = 0; p < 3; ++p) {
                uint32_t aoff = (p == 2) ? (uint32_t)ALO : (uint32_t)AHI;
                uint32_t boff = (p == 1) ? (uint32_t)BLO : (uint32_t)BHI;
                uint32_t a[2][4];
#pragma unroll
                for (int t = 0; t < 2; ++t) {
                    uint32_t addr = sb + aoff + aRow + (uint32_t)(t * 16 * ROWB) + (uint32_t)(ks * 32);
                    LDSM_X4(a[t][0], a[t][1], a[t][2], a[t][3], addr);
                }
#pragma unroll
                for (int pr = 0; pr < 4; ++pr) {
                    uint32_t baddr = sb + boff + bRow + (uint32_t)(pr * 16 * ROWB) + (uint32_t)(ks * 32);
                    uint32_t b0, b1, b2, b3;
                    LDSM_X4(b0, b1, b2, b3, baddr);
#pragma unroll
                    for (int t = 0; t < 2; ++t) {
                        mma_bf16(acc[t][pr * 2 + 0], a[t], b0, b1);
                        mma_bf16(acc[t][pr * 2 + 1], a[t], b2, b3);
                    }
                }
            }
        }
    };

    // -------- pipelined main loop --------
    prefetch(0);
    store_stage(0);
    __syncthreads();
    for (int c = 0; c < nch; ++c) {
        int cur = c & 1;
        if (c + 1 < nch) prefetch(c + 1);
        compute(cur);
        if (c + 1 < nch) store_stage(cur ^ 1);
        __syncthreads();
    }

    // -------- epilogue: bias + relu + store --------
#pragma unroll
    for (int t = 0; t < 2; ++t) {
        int row = row0 + m0w + t * 16 + (lane >> 2);
#pragma unroll
        for (int nt = 0; nt < 8; ++nt) {
            int col = n0 + n0w + nt * 8 + (lane & 3) * 2;
            float2 bb = __ldg((const float2*)(bias + col));
            float v0 = acc[t][nt][0] + bb.x;
            float v1 = acc[t][nt][1] + bb.y;
            float v2 = acc[t][nt][2] + bb.x;
            float v3 = acc[t][nt][3] + bb.y;
            if (doRelu) {
                v0 = fmaxf(v0, 0.f); v1 = fmaxf(v1, 0.f);
                v2 = fmaxf(v2, 0.f); v3 = fmaxf(v3, 0.f);
            }
            if (row < M) {
                float2 o; o.x = v0; o.y = v1;
                *(float2*)(C + (size_t)row * HID + col) = o;
            }
            if (row + 8 < M) {
                float2 o; o.x = v2; o.y = v3;
                *(float2*)(C + (size_t)(row + 8) * HID + col) = o;
            }
        }
    }
}

// ---------------- link feature gather ----------------
__global__ void gather_kernel(const void* __restrict__ srcI,
                              const void* __restrict__ dstI,
                              const float* __restrict__ h2,
                              float* __restrict__ comb) {
    int t = blockIdx.x * blockDim.x + threadIdx.x;
    if (t >= NL * HID) return;
    int l = t >> 8;
    int k = t & 255;
    long long s_n = getIdx(srcI, l);
    long long d_n = getIdx(dstI, l);
    float s = h2[s_n * HID + k];
    float d = h2[d_n * HID + k];
    float* c = comb + (long long)l * (4 * HID);
    c[k] = s;
    c[HID + k] = d;
    c[2 * HID + k] = s * d;
    c[3 * HID + k] = fabsf(s - d);
}

// ---------------- final: sigmoid(hidden . wp2 + b), warp per link ----------------
__global__ void final_kernel(const float* __restrict__ hid,
                             const float* __restrict__ wp2,
                             const float* __restrict__ bp2,
                             float* __restrict__ out) {
    int gtid = blockIdx.x * blockDim.x + threadIdx.x;
    int w = gtid >> 5;
    int lane = gtid & 31;
    if (w >= NL) return;
    const float* h = hid + (long long)w * HID;
    float s = 0.f;
#pragma unroll
    for (int j = 0; j < HID / 32; ++j) {
        int c = lane + j * 32;
        s = fmaf(h[c], wp2[c], s);
    }
#pragma unroll
    for (int o = 16; o > 0; o >>= 1)
        s += __shfl_down_sync(0xffffffffu, s, o);
    if (lane == 0) {
        float logit = s + bp2[0];
        out[w] = 1.0f / (1.0f + expf(-logit));
    }
}

// ---------------- launcher ----------------
extern "C" void kernel_launch(void* const* d_in, const int* in_sizes, int n_in,
                              void* d_out, int out_size) {
    const float* x     = (const float*)d_in[0];
    const void*  ei    = d_in[1];
    const void*  srcI  = d_in[3];
    const void*  dstI  = d_in[4];
    const float* w_emb = (const float*)d_in[5];
    const float* b_emb = (const float*)d_in[6];
    const float* wl0   = (const float*)d_in[8];
    const float* bl0   = (const float*)d_in[9];
    const float* wr0   = (const float*)d_in[10];
    const float* wl1   = (const float*)d_in[13];
    const float* bl1   = (const float*)d_in[14];
    const float* wr1   = (const float*)d_in[15];
    const float* wp1   = (const float*)d_in[18];
    const float* bp1   = (const float*)d_in[19];
    const float* wp2   = (const float*)d_in[20];
    const float* bp2   = (const float*)d_in[21];
    float* out = (float*)d_out;

    float *h0, *h1, *agg, *deg, *comb, *hid;
    cudaGetSymbolAddress((void**)&h0,   g_h0);
    cudaGetSymbolAddress((void**)&h1,   g_h1);
    cudaGetSymbolAddress((void**)&agg,  g_agg);
    cudaGetSymbolAddress((void**)&deg,  g_deg);
    cudaGetSymbolAddress((void**)&comb, g_comb);
    cudaGetSymbolAddress((void**)&hid,  g_hid);

    cudaFuncSetAttribute(gemm_mma, cudaFuncAttributeMaxDynamicSharedMemorySize, GEMM_SMEM);

    dim3 gridN((NN + 127) / 128, 2);
    dim3 gridL((NL + 127) / 128, 2);

    // 0. detect index width
    detect_kernel<<<1, 256>>>((const int*)ei);

    // 1. degree + zero agg
    cudaMemsetAsync(deg, 0, NN * sizeof(float));
    cudaMemsetAsync(agg, 0, (size_t)NN * HID * sizeof(float));
    deg_kernel<<<(NE + 255) / 256, 256>>>(ei, deg);

    // 2. embedding: h0 = x @ w_emb^T + b_emb
    gemm_mma<<<gridN, 256, GEMM_SMEM>>>(x, FEAT, nullptr, nullptr,
                                        nullptr, 0, w_emb, nullptr,
                                        b_emb, h0, NN, 0);

    // 3. layer 0: relu(lin_l((agg+h0)/(deg+1)) + lin_r(h0))
    scatter_kernel<<<(NE * 32 + 255) / 256, 256>>>(ei, h0, agg);
    gemm_mma<<<gridN, 256, GEMM_SMEM>>>(agg, HID, h0, deg,
                                        h0, HID, wl0, wr0,
                                        bl0, h1, NN, 1);

    // 4. layer 1 (h2 written into h0 buffer)
    cudaMemsetAsync(agg, 0, (size_t)NN * HID * sizeof(float));
    scatter_kernel<<<(NE * 32 + 255) / 256, 256>>>(ei, h1, agg);
    gemm_mma<<<gridN, 256, GEMM_SMEM>>>(agg, HID, h1, deg,
                                        h1, HID, wl1, wr1,
                                        bl1, h0, NN, 1);

    // 5. link head
    gather_kernel<<<(NL * HID + 255) / 256, 256>>>(srcI, dstI, h0, comb);
    gemm_mma<<<gridL, 256, GEMM_SMEM>>>(comb, 4 * HID, nullptr, nullptr,
                                        nullptr, 0, wp1, nullptr,
                                        bp1, hid, NL, 1);
    final_kernel<<<(NL * 32 + 255) / 256, 256>>>(hid, wp2, bp2, out);
}

// round 5
// speedup vs baseline: 1.5400x; 1.2189x over previous
#include <cuda_runtime.h>
#include <cuda_bf16.h>
#include <cstdint>
#include <math.h>

#define NN   100000
#define NE   500000
#define FEAT 128
#define HID  256
#define NL   16384

// ---------------- scratch (no allocations allowed) ----------------
__device__ float g_h0[NN * HID];              // h0 / h2
__device__ float g_h1[NN * HID];              // h1
__device__ float g_agg[NN * HID];             // neighbor sum
__device__ float g_deg[NN];
__device__ float g_hid[NL * HID];
__device__ int   g_is64;

// bf16 hi/lo planes
__device__ __nv_bfloat16 g_aH[(size_t)NN * 512];   // [mean | h] activation, K=512
__device__ __nv_bfloat16 g_aL[(size_t)NN * 512];
__device__ __nv_bfloat16 g_xH[(size_t)NN * 128];
__device__ __nv_bfloat16 g_xL[(size_t)NN * 128];
__device__ __nv_bfloat16 g_cH[(size_t)NL * 1024];  // link features
__device__ __nv_bfloat16 g_cL[(size_t)NL * 1024];
__device__ __nv_bfloat16 g_weH[256 * 128],  g_weL[256 * 128];
__device__ __nv_bfloat16 g_w0H[256 * 512],  g_w0L[256 * 512];
__device__ __nv_bfloat16 g_w1H[256 * 512],  g_w1L[256 * 512];
__device__ __nv_bfloat16 g_wpH[256 * 1024], g_wpL[256 * 1024];

// ---------------- helpers ----------------
__device__ __forceinline__ uint32_t smem_u32(const void* p) {
    uint32_t a;
    asm("{ .reg .u64 t; cvta.to.shared.u64 t, %1; cvt.u32.u64 %0, t; }" : "=r"(a) : "l"(p));
    return a;
}

#define LDSM_X4(r0, r1, r2, r3, addr) \
    asm volatile("ldmatrix.sync.aligned.m8n8.x4.shared.b16 {%0,%1,%2,%3}, [%4];" \
                 : "=r"(r0), "=r"(r1), "=r"(r2), "=r"(r3) : "r"(addr))

__device__ __forceinline__ void mma_bf16(float* d, const uint32_t* a,
                                         uint32_t b0, uint32_t b1) {
    asm volatile(
        "mma.sync.aligned.m16n8k16.row.col.f32.bf16.bf16.f32 "
        "{%0,%1,%2,%3}, {%4,%5,%6,%7}, {%8,%9}, {%0,%1,%2,%3};"
        : "+f"(d[0]), "+f"(d[1]), "+f"(d[2]), "+f"(d[3])
        : "r"(a[0]), "r"(a[1]), "r"(a[2]), "r"(a[3]), "r"(b0), "r"(b1));
}

__device__ __forceinline__ void split1(float v, __nv_bfloat16& h, __nv_bfloat16& l) {
    h = __float2bfloat16_rn(v);
    l = __float2bfloat16_rn(v - __bfloat162float(h));
}
__device__ __forceinline__ void split2(float x, float y, uint32_t& hi, uint32_t& lo) {
    __nv_bfloat16 hx, lx, hy, ly;
    split1(x, hx, lx);
    split1(y, hy, ly);
    hi = (uint32_t)__bfloat16_as_ushort(hx) | ((uint32_t)__bfloat16_as_ushort(hy) << 16);
    lo = (uint32_t)__bfloat16_as_ushort(lx) | ((uint32_t)__bfloat16_as_ushort(ly) << 16);
}

// ---------------- index dtype detection ----------------
__global__ void detect_kernel(const int* __restrict__ words) {
    __shared__ int nz;
    if (threadIdx.x == 0) nz = 0;
    __syncthreads();
    if (words[threadIdx.x * 2 + 1] != 0) atomicExch(&nz, 1);
    __syncthreads();
    if (threadIdx.x == 0) g_is64 = (nz == 0) ? 1 : 0;
}
__device__ __forceinline__ long long getIdx(const void* p, long long i) {
    if (g_is64) return ((const long long*)p)[i];
    return (long long)((const int*)p)[i];
}

// ---------------- degree ----------------
__global__ void deg_kernel(const void* __restrict__ ei, float* __restrict__ deg) {
    int e = blockIdx.x * blockDim.x + threadIdx.x;
    if (e < NE) {
        long long dst = getIdx(ei, (long long)NE + e);
        atomicAdd(&deg[dst], 1.0f);
    }
}

// ---------------- scatter: agg[dst] += h[src], warp/edge, vec4 red ----------------
__global__ void scatter_kernel(const void* __restrict__ ei,
                               const float* __restrict__ h,
                               float* __restrict__ agg) {
    int gtid = blockIdx.x * blockDim.x + threadIdx.x;
    int w = gtid >> 5;
    int lane = gtid & 31;
    if (w >= NE) return;
    long long src = getIdx(ei, w);
    long long dst = getIdx(ei, (long long)NE + w);
    const float4* hs = (const float4*)(h + src * HID);
    float4* ad = (float4*)(agg + dst * HID);
#pragma unroll
    for (int j = 0; j < 2; ++j) {
        float4 v = __ldg(hs + lane + j * 32);
        asm volatile("red.global.add.v4.f32 [%0], {%1, %2, %3, %4};"
                     :: "l"(ad + lane + j * 32), "f"(v.x), "f"(v.y), "f"(v.z), "f"(v.w)
                     : "memory");
    }
}

// ---------------- weight pack: split W[256,Ks] into dst planes at colOff ----------------
__global__ void pack_w(const float* __restrict__ w,
                       __nv_bfloat16* __restrict__ dH, __nv_bfloat16* __restrict__ dL,
                       int Ks, int Kd, int colOff) {
    int i = blockIdx.x * blockDim.x + threadIdx.x;
    if (i >= 256 * Ks) return;
    int r = i / Ks, c = i % Ks;
    __nv_bfloat16 h, l;
    split1(w[i], h, l);
    dH[(size_t)r * Kd + colOff + c] = h;
    dL[(size_t)r * Kd + colOff + c] = l;
}

// ---------------- x split ----------------
__global__ void split_x(const float* __restrict__ x,
                        __nv_bfloat16* __restrict__ dH, __nv_bfloat16* __restrict__ dL) {
    size_t i = (size_t)blockIdx.x * blockDim.x + threadIdx.x;
    if (i >= (size_t)NN * 128) return;
    __nv_bfloat16 h, l;
    split1(x[i], h, l);
    dH[i] = h;
    dL[i] = l;
}

// ---------------- mean split: a[:,0:256] = split((agg+h)/(deg+1)) ----------------
__global__ void mean_split(const float* __restrict__ agg, const float* __restrict__ h,
                           const float* __restrict__ deg,
                           __nv_bfloat16* __restrict__ aH, __nv_bfloat16* __restrict__ aL) {
    int i = blockIdx.x * blockDim.x + threadIdx.x;   // float4 index
    if (i >= NN * 64) return;
    int row = i >> 6;
    int c4 = (i & 63) * 4;
    float inv = 1.0f / (__ldg(deg + row) + 1.0f);
    float4 a = ((const float4*)agg)[i];
    float4 hv = ((const float4*)h)[i];
    float v0 = (a.x + hv.x) * inv, v1 = (a.y + hv.y) * inv;
    float v2 = (a.z + hv.z) * inv, v3 = (a.w + hv.w) * inv;
    uint32_t h01, l01, h23, l23;
    split2(v0, v1, h01, l01);
    split2(v2, v3, h23, l23);
    size_t base = (size_t)row * 512 + c4;
    *(uint32_t*)(aH + base) = h01;
    *(uint32_t*)(aH + base + 2) = h23;
    *(uint32_t*)(aL + base) = l01;
    *(uint32_t*)(aL + base + 2) = l23;
}

// ---------------- bf16 pipelined tensor GEMM ----------------
// C[M,256] = act(A @ W^T + bias); A = AH + AL (hi/lo planes, [M,K] bf16),
// W = WH + WL ([256,K] bf16). 3 passes: AH*WH + AH*WL + AL*WH.
// CTA tile 128x256, 512 threads (warp grid 4Mx4N, warp tile 32x64), KC=64,
// 2-stage cp.async double buffer, XOR-swizzled SMEM.
#define KC 64
#define A_PL   16384            // 128 rows * 128B
#define B_PL   32768            // 256 rows * 128B
#define STG    (2 * A_PL + 2 * B_PL)   // 98304
#define GEMM_SMEM (2 * STG)            // 196608

__global__ __launch_bounds__(512, 1)
void gemm_bf16(const __nv_bfloat16* __restrict__ AH, const __nv_bfloat16* __restrict__ AL,
               int K,
               const __nv_bfloat16* __restrict__ WH, const __nv_bfloat16* __restrict__ WL,
               const float* __restrict__ bias, float* __restrict__ C, int M, int doRelu,
               __nv_bfloat16* outH, __nv_bfloat16* outL, int outColOff, int outStride) {
    extern __shared__ char smem[];
    const uint32_t sbase = smem_u32(smem);
    const int tid = threadIdx.x;
    const int lane = tid & 31;
    const int wid = tid >> 5;
    const int wm = wid & 3;
    const int wn = wid >> 2;
    const int m0w = wm * 32;
    const int n0w = wn * 64;
    const int row0 = blockIdx.x * 128;
    const int nch = K / KC;

    float acc[2][8][4];
#pragma unroll
    for (int t = 0; t < 2; ++t)
#pragma unroll
        for (int n = 0; n < 8; ++n)
#pragma unroll
            for (int j = 0; j < 4; ++j) acc[t][n][j] = 0.0f;

    // ---- async load of chunk c into stage c&1 ----
    auto issue = [&](int c) {
        uint32_t sb = sbase + (c & 1) * STG;
        int kk = c * KC;
        // A planes: 2048 x 16B
#pragma unroll
        for (int i = 0; i < 4; ++i) {
            int idx = tid + i * 512;
            int plane = idx >> 10;
            int rem = idx & 1023;
            int row = rem >> 3, slot = rem & 7;
            uint32_t dst = sb + plane * A_PL + row * 128 + ((slot ^ (row & 7)) << 4);
            int grow = row0 + row;
            int ok = grow < M;
            size_t srow = ok ? (size_t)grow : 0;
            const __nv_bfloat16* src = (plane ? AL : AH) + srow * K + kk + slot * 8;
            int sz = ok ? 16 : 0;
            asm volatile("cp.async.cg.shared.global [%0], [%1], 16, %2;"
                         :: "r"(dst), "l"(src), "r"(sz));
        }
        // W planes: 4096 x 16B
#pragma unroll
        for (int i = 0; i < 8; ++i) {
            int idx = tid + i * 512;
            int plane = idx >> 11;
            int rem = idx & 2047;
            int row = rem >> 3, slot = rem & 7;
            uint32_t dst = sb + 2 * A_PL + plane * B_PL + row * 128 + ((slot ^ (row & 7)) << 4);
            const __nv_bfloat16* src = (plane ? WL : WH) + (size_t)row * K + kk + slot * 8;
            asm volatile("cp.async.cg.shared.global [%0], [%1], 16;"
                         :: "r"(dst), "l"(src));
        }
        asm volatile("cp.async.commit_group;" ::: "memory");
    };

    // ldmatrix lane constants
    const int rowA = m0w + (lane & 15);
    const int hiA = lane >> 4;
    const int xa = rowA & 7;
    const uint32_t aBase = (uint32_t)rowA * 128;
    const int nb = (lane < 16) ? (lane & 7) : 8 + (lane & 7);
    const int rowB = n0w + nb;
    const int hiB = (lane >> 3) & 1;
    const int xb = rowB & 7;
    const uint32_t bBase = (uint32_t)rowB * 128;

    auto compute = [&](int c) {
        uint32_t sb = sbase + (c & 1) * STG;
#pragma unroll
        for (int p = 0; p < 3; ++p) {
            uint32_t Ab = sb + (p == 2 ? A_PL : 0);
            uint32_t Bb = sb + 2 * A_PL + (p == 1 ? B_PL : 0);
#pragma unroll
            for (int ks = 0; ks < 4; ++ks) {
                uint32_t sa = (uint32_t)(((2 * ks + hiA) ^ xa) << 4);
                uint32_t sbb = (uint32_t)(((2 * ks + hiB) ^ xb) << 4);
                uint32_t a[2][4];
#pragma unroll
                for (int t = 0; t < 2; ++t) {
                    uint32_t addr = Ab + aBase + (uint32_t)(t * 2048) + sa;
                    LDSM_X4(a[t][0], a[t][1], a[t][2], a[t][3], addr);
                }
#pragma unroll
                for (int pr = 0; pr < 4; ++pr) {
                    uint32_t baddr = Bb + bBase + (uint32_t)(pr * 2048) + sbb;
                    uint32_t b0, b1, b2, b3;
                    LDSM_X4(b0, b1, b2, b3, baddr);
#pragma unroll
                    for (int t = 0; t < 2; ++t) {
                        mma_bf16(acc[t][pr * 2 + 0], a[t], b0, b1);
                        mma_bf16(acc[t][pr * 2 + 1], a[t], b2, b3);
                    }
                }
            }
        }
    };

    issue(0);
    for (int c = 0; c < nch; ++c) {
        if (c + 1 < nch) {
            issue(c + 1);
            asm volatile("cp.async.wait_group 1;" ::: "memory");
        } else {
            asm volatile("cp.async.wait_group 0;" ::: "memory");
        }
        __syncthreads();
        compute(c);
        __syncthreads();
    }

    // ---- epilogue: bias + relu + fp32 store (+ optional bf16 split store) ----
#pragma unroll
    for (int t = 0; t < 2; ++t) {
        int row = row0 + m0w + t * 16 + (lane >> 2);
#pragma unroll
        for (int nt = 0; nt < 8; ++nt) {
            int col = n0w + nt * 8 + (lane & 3) * 2;
            float2 bb = __ldg((const float2*)(bias + col));
            float v0 = acc[t][nt][0] + bb.x;
            float v1 = acc[t][nt][1] + bb.y;
            float v2 = acc[t][nt][2] + bb.x;
            float v3 = acc[t][nt][3] + bb.y;
            if (doRelu) {
                v0 = fmaxf(v0, 0.f); v1 = fmaxf(v1, 0.f);
                v2 = fmaxf(v2, 0.f); v3 = fmaxf(v3, 0.f);
            }
            if (row < M) {
                float2 o; o.x = v0; o.y = v1;
                *(float2*)(C + (size_t)row * HID + col) = o;
                if (outH) {
                    uint32_t h01, l01;
                    split2(v0, v1, h01, l01);
                    size_t ob = (size_t)row * outStride + outColOff + col;
                    *(uint32_t*)(outH + ob) = h01;
                    *(uint32_t*)(outL + ob) = l01;
                }
            }
            if (row + 8 < M) {
                float2 o; o.x = v2; o.y = v3;
                *(float2*)(C + (size_t)(row + 8) * HID + col) = o;
                if (outH) {
                    uint32_t h23, l23;
                    split2(v2, v3, h23, l23);
                    size_t ob = (size_t)(row + 8) * outStride + outColOff + col;
                    *(uint32_t*)(outH + ob) = h23;
                    *(uint32_t*)(outL + ob) = l23;
                }
            }
        }
    }
}

// ---------------- link feature gather -> bf16 split planes ----------------
__global__ void gather_split(const void* __restrict__ srcI,
                             const void* __restrict__ dstI,
                             const float* __restrict__ h2,
                             __nv_bfloat16* __restrict__ cH,
                             __nv_bfloat16* __restrict__ cL) {
    int t = blockIdx.x * blockDim.x + threadIdx.x;
    if (t >= NL * HID) return;
    int l = t >> 8;
    int k = t & 255;
    long long s_n = getIdx(srcI, l);
    long long d_n = getIdx(dstI, l);
    float s = h2[s_n * HID + k];
    float d = h2[d_n * HID + k];
    float f[4] = {s, d, s * d, fabsf(s - d)};
    size_t base = (size_t)l * 1024 + k;
#pragma unroll
    for (int j = 0; j < 4; ++j) {
        __nv_bfloat16 h, lo;
        split1(f[j], h, lo);
        cH[base + j * 256] = h;
        cL[base + j * 256] = lo;
    }
}

// ---------------- final: sigmoid(hidden . wp2 + b), warp per link ----------------
__global__ void final_kernel(const float* __restrict__ hid,
                             const float* __restrict__ wp2,
                             const float* __restrict__ bp2,
                             float* __restrict__ out) {
    int gtid = blockIdx.x * blockDim.x + threadIdx.x;
    int w = gtid >> 5;
    int lane = gtid & 31;
    if (w >= NL) return;
    const float* h = hid + (long long)w * HID;
    float s = 0.f;
#pragma unroll
    for (int j = 0; j < HID / 32; ++j) {
        int c = lane + j * 32;
        s = fmaf(h[c], wp2[c], s);
    }
#pragma unroll
    for (int o = 16; o > 0; o >>= 1)
        s += __shfl_down_sync(0xffffffffu, s, o);
    if (lane == 0) {
        float logit = s + bp2[0];
        out[w] = 1.0f / (1.0f + expf(-logit));
    }
}

// ---------------- launcher ----------------
extern "C" void kernel_launch(void* const* d_in, const int* in_sizes, int n_in,
                              void* d_out, int out_size) {
    const float* x     = (const float*)d_in[0];
    const void*  ei    = d_in[1];
    const void*  srcI  = d_in[3];
    const void*  dstI  = d_in[4];
    const float* w_emb = (const float*)d_in[5];
    const float* b_emb = (const float*)d_in[6];
    const float* wl0   = (const float*)d_in[8];
    const float* bl0   = (const float*)d_in[9];
    const float* wr0   = (const float*)d_in[10];
    const float* wl1   = (const float*)d_in[13];
    const float* bl1   = (const float*)d_in[14];
    const float* wr1   = (const float*)d_in[15];
    const float* wp1   = (const float*)d_in[18];
    const float* bp1   = (const float*)d_in[19];
    const float* wp2   = (const float*)d_in[20];
    const float* bp2   = (const float*)d_in[21];
    float* out = (float*)d_out;

    float *h0, *h1, *agg, *deg, *hid;
    __nv_bfloat16 *aH, *aL, *xH, *xL, *cH, *cL;
    __nv_bfloat16 *weH, *weL, *w0H, *w0L, *w1H, *w1L, *wpH, *wpL;
    cudaGetSymbolAddress((void**)&h0,  g_h0);
    cudaGetSymbolAddress((void**)&h1,  g_h1);
    cudaGetSymbolAddress((void**)&agg, g_agg);
    cudaGetSymbolAddress((void**)&deg, g_deg);
    cudaGetSymbolAddress((void**)&hid, g_hid);
    cudaGetSymbolAddress((void**)&aH,  g_aH);
    cudaGetSymbolAddress((void**)&aL,  g_aL);
    cudaGetSymbolAddress((void**)&xH,  g_xH);
    cudaGetSymbolAddress((void**)&xL,  g_xL);
    cudaGetSymbolAddress((void**)&cH,  g_cH);
    cudaGetSymbolAddress((void**)&cL,  g_cL);
    cudaGetSymbolAddress((void**)&weH, g_weH);
    cudaGetSymbolAddress((void**)&weL, g_weL);
    cudaGetSymbolAddress((void**)&w0H, g_w0H);
    cudaGetSymbolAddress((void**)&w0L, g_w0L);
    cudaGetSymbolAddress((void**)&w1H, g_w1H);
    cudaGetSymbolAddress((void**)&w1L, g_w1L);
    cudaGetSymbolAddress((void**)&wpH, g_wpH);
    cudaGetSymbolAddress((void**)&wpL, g_wpL);

    cudaFuncSetAttribute(gemm_bf16, cudaFuncAttributeMaxDynamicSharedMemorySize, GEMM_SMEM);

    dim3 gridN((NN + 127) / 128);
    dim3 gridL(NL / 128);

    // 0. detect index width
    detect_kernel<<<1, 256>>>((const int*)ei);

    // 1. degree + zero agg; pack weights; split x
    cudaMemsetAsync(deg, 0, NN * sizeof(float));
    cudaMemsetAsync(agg, 0, (size_t)NN * HID * sizeof(float));
    deg_kernel<<<(NE + 255) / 256, 256>>>(ei, deg);
    pack_w<<<(256 * 128 + 255) / 256, 256>>>(w_emb, weH, weL, 128, 128, 0);
    pack_w<<<(256 * 256 + 255) / 256, 256>>>(wl0, w0H, w0L, 256, 512, 0);
    pack_w<<<(256 * 256 + 255) / 256, 256>>>(wr0, w0H, w0L, 256, 512, 256);
    pack_w<<<(256 * 256 + 255) / 256, 256>>>(wl1, w1H, w1L, 256, 512, 0);
    pack_w<<<(256 * 256 + 255) / 256, 256>>>(wr1, w1H, w1L, 256, 512, 256);
    pack_w<<<(256 * 1024 + 255) / 256, 256>>>(wp1, wpH, wpL, 1024, 1024, 0);
    split_x<<<(NN * 128 + 255) / 256, 256>>>(x, xH, xL);

    // 2. embedding: h0 = x @ w_emb^T + b_emb; epilogue splits h0 into a[:,256:512)
    gemm_bf16<<<gridN, 512, GEMM_SMEM>>>(xH, xL, 128, weH, weL, b_emb, h0, NN, 0,
                                         aH, aL, 256, 512);

    // 3. layer 0
    scatter_kernel<<<(NE * 32 + 255) / 256, 256>>>(ei, h0, agg);
    mean_split<<<(NN * 64 + 255) / 256, 256>>>(agg, h0, deg, aH, aL);
    gemm_bf16<<<gridN, 512, GEMM_SMEM>>>(aH, aL, 512, w0H, w0L, bl0, h1, NN, 1,
                                         aH, aL, 256, 512);

    // 4. layer 1 (h2 into h0 buffer)
    cudaMemsetAsync(agg, 0, (size_t)NN * HID * sizeof(float));
    scatter_kernel<<<(NE * 32 + 255) / 256, 256>>>(ei, h1, agg);
    mean_split<<<(NN * 64 + 255) / 256, 256>>>(agg, h1, deg, aH, aL);
    gemm_bf16<<<gridN, 512, GEMM_SMEM>>>(aH, aL, 512, w1H, w1L, bl1, h0, NN, 1,
                                         nullptr, nullptr, 0, 0);

    // 5. link head
    gather_split<<<(NL * HID + 255) / 256, 256>>>(srcI, dstI, h0, cH, cL);
    gemm_bf16<<<gridL, 512, GEMM_SMEM>>>(cH, cL, 1024, wpH, wpL, bp1, hid, NL, 1,
                                         nullptr, nullptr, 0, 0);
    final_kernel<<<(NL * 32 + 255) / 256, 256>>>(hid, wp2, bp2, out);
}

// round 6
// speedup vs baseline: 1.6268x; 1.0563x over previous
#include <cuda_runtime.h>
#include <cuda_bf16.h>
#include <cstdint>
#include <math.h>

#define NN   100000
#define NNP  100096        // padded to multiple of 128
#define NE   500000
#define FEAT 128
#define HID  256
#define NL   16384

// ---------------- scratch (no allocations allowed) ----------------
__device__ float g_h0[NN * HID];
__device__ float g_h1[NN * HID];
__device__ float g_agg[NN * HID];
__device__ float g_deg[NN];
__device__ float g_hid[NL * HID];
__device__ int   g_is64;

// bf16 planes, chunk-major pre-swizzled: [kchunk][row][64]
__device__ __align__(128) __nv_bfloat16 g_aH[(size_t)8 * NNP * 64];
__device__ __align__(128) __nv_bfloat16 g_aL[(size_t)8 * NNP * 64];
__device__ __align__(128) __nv_bfloat16 g_xH[(size_t)2 * NNP * 64];
__device__ __align__(128) __nv_bfloat16 g_xL[(size_t)2 * NNP * 64];
__device__ __align__(128) __nv_bfloat16 g_cH[(size_t)16 * NL * 64];
__device__ __align__(128) __nv_bfloat16 g_cL[(size_t)16 * NL * 64];
__device__ __align__(128) __nv_bfloat16 g_weH[2 * 256 * 64],  g_weL[2 * 256 * 64];
__device__ __align__(128) __nv_bfloat16 g_w0H[8 * 256 * 64],  g_w0L[8 * 256 * 64];
__device__ __align__(128) __nv_bfloat16 g_w1H[8 * 256 * 64],  g_w1L[8 * 256 * 64];
__device__ __align__(128) __nv_bfloat16 g_wpH[16 * 256 * 64], g_wpL[16 * 256 * 64];

// ---------------- helpers ----------------
__device__ __forceinline__ uint32_t smem_u32(const void* p) {
    uint32_t a;
    asm("{ .reg .u64 t; cvta.to.shared.u64 t, %1; cvt.u32.u64 %0, t; }" : "=r"(a) : "l"(p));
    return a;
}
// swizzled element offset within a 64-element (128B) row; c in [0,64)
__device__ __forceinline__ int swcol(int row, int c) {
    return (((c >> 3) ^ (row & 7)) << 3) + (c & 7);
}

#define LDSM_X4(r0, r1, r2, r3, addr) \
    asm volatile("ldmatrix.sync.aligned.m8n8.x4.shared.b16 {%0,%1,%2,%3}, [%4];" \
                 : "=r"(r0), "=r"(r1), "=r"(r2), "=r"(r3) : "r"(addr))

__device__ __forceinline__ void mma_bf16(float* d, const uint32_t* a,
                                         uint32_t b0, uint32_t b1) {
    asm volatile(
        "mma.sync.aligned.m16n8k16.row.col.f32.bf16.bf16.f32 "
        "{%0,%1,%2,%3}, {%4,%5,%6,%7}, {%8,%9}, {%0,%1,%2,%3};"
        : "+f"(d[0]), "+f"(d[1]), "+f"(d[2]), "+f"(d[3])
        : "r"(a[0]), "r"(a[1]), "r"(a[2]), "r"(a[3]), "r"(b0), "r"(b1));
}

__device__ __forceinline__ void split1(float v, __nv_bfloat16& h, __nv_bfloat16& l) {
    h = __float2bfloat16_rn(v);
    l = __float2bfloat16_rn(v - __bfloat162float(h));
}
__device__ __forceinline__ void split2(float x, float y, uint32_t& hi, uint32_t& lo) {
    __nv_bfloat16 hx, lx, hy, ly;
    split1(x, hx, lx);
    split1(y, hy, ly);
    hi = (uint32_t)__bfloat16_as_ushort(hx) | ((uint32_t)__bfloat16_as_ushort(hy) << 16);
    lo = (uint32_t)__bfloat16_as_ushort(lx) | ((uint32_t)__bfloat16_as_ushort(ly) << 16);
}

__device__ __forceinline__ void mbar_init(uint32_t addr, uint32_t cnt) {
    asm volatile("mbarrier.init.shared.b64 [%0], %1;" :: "r"(addr), "r"(cnt) : "memory");
}
__device__ __forceinline__ void mbar_expect_tx(uint32_t addr, uint32_t tx) {
    asm volatile("mbarrier.arrive.expect_tx.shared.b64 _, [%0], %1;"
                 :: "r"(addr), "r"(tx) : "memory");
}
__device__ __forceinline__ void mbar_wait(uint32_t addr, uint32_t parity) {
    uint32_t done;
    do {
        asm volatile(
            "{\n\t.reg .pred p;\n\t"
            "mbarrier.try_wait.parity.acquire.cta.shared::cta.b64 p, [%1], %2, 0x989680;\n\t"
            "selp.b32 %0, 1, 0, p;\n\t}"
            : "=r"(done) : "r"(addr), "r"(parity) : "memory");
    } while (!done);
}
__device__ __forceinline__ void bulk_g2s(uint32_t dst, const void* src, uint32_t bytes,
                                         uint32_t mbar) {
    asm volatile(
        "cp.async.bulk.shared::cluster.global.mbarrier::complete_tx::bytes [%0], [%1], %2, [%3];"
        :: "r"(dst), "l"(src), "r"(bytes), "r"(mbar) : "memory");
}

// ---------------- index dtype detection ----------------
__global__ void detect_kernel(const int* __restrict__ words) {
    __shared__ int nz;
    if (threadIdx.x == 0) nz = 0;
    __syncthreads();
    if (words[threadIdx.x * 2 + 1] != 0) atomicExch(&nz, 1);
    __syncthreads();
    if (threadIdx.x == 0) g_is64 = (nz == 0) ? 1 : 0;
}
__device__ __forceinline__ long long getIdx(const void* p, long long i) {
    if (g_is64) return ((const long long*)p)[i];
    return (long long)((const int*)p)[i];
}

// ---------------- zero ----------------
__global__ void zero_kernel(float* __restrict__ p, int n) {
    int i = blockIdx.x * blockDim.x + threadIdx.x;
    int stride = gridDim.x * blockDim.x;
    for (; i < n; i += stride) p[i] = 0.0f;
}

// ---------------- degree ----------------
__global__ void deg_kernel(const void* __restrict__ ei, float* __restrict__ deg) {
    int e = blockIdx.x * blockDim.x + threadIdx.x;
    if (e < NE) {
        long long dst = getIdx(ei, (long long)NE + e);
        atomicAdd(&deg[dst], 1.0f);
    }
}

// ---------------- scatter: agg[dst] += h[src], warp/edge, vec4 red ----------------
__global__ void scatter_kernel(const void* __restrict__ ei,
                               const float* __restrict__ h,
                               float* __restrict__ agg) {
    int gtid = blockIdx.x * blockDim.x + threadIdx.x;
    int w = gtid >> 5;
    int lane = gtid & 31;
    if (w >= NE) return;
    long long src = getIdx(ei, w);
    long long dst = getIdx(ei, (long long)NE + w);
    const float4* hs = (const float4*)(h + src * HID);
    float4* ad = (float4*)(agg + dst * HID);
#pragma unroll
    for (int j = 0; j < 2; ++j) {
        float4 v = __ldg(hs + lane + j * 32);
        asm volatile("red.global.add.v4.f32 [%0], {%1, %2, %3, %4};"
                     :: "l"(ad + lane + j * 32), "f"(v.x), "f"(v.y), "f"(v.z), "f"(v.w)
                     : "memory");
    }
}

// ---------------- weight pack into chunk-major swizzled planes ----------------
__global__ void pack_w(const float* __restrict__ w,
                       __nv_bfloat16* __restrict__ dH, __nv_bfloat16* __restrict__ dL,
                       int Ks, int colOff) {
    int i = blockIdx.x * blockDim.x + threadIdx.x;
    if (i >= 256 * Ks) return;
    int r = i / Ks, c = i % Ks;
    int gc = colOff + c;
    size_t idx = (size_t)(gc >> 6) * (256 * 64) + (size_t)r * 64 + swcol(r, gc & 63);
    __nv_bfloat16 h, l;
    split1(w[i], h, l);
    dH[idx] = h;
    dL[idx] = l;
}

// ---------------- x split into chunk-major swizzled planes ----------------
__global__ void split_x(const float* __restrict__ x,
                        __nv_bfloat16* __restrict__ dH, __nv_bfloat16* __restrict__ dL) {
    int i = blockIdx.x * blockDim.x + threadIdx.x;   // float4 index
    if (i >= NN * 32) return;
    int row = i >> 5;
    int c = (i & 31) * 4;                            // col in [0,128)
    float4 v = ((const float4*)x)[i];
    uint32_t h01, l01, h23, l23;
    split2(v.x, v.y, h01, l01);
    split2(v.z, v.w, h23, l23);
    size_t base = (size_t)(c >> 6) * ((size_t)NNP * 64) + (size_t)row * 64 + swcol(row, c & 63);
    *(uint32_t*)(dH + base) = h01;
    *(uint32_t*)(dH + base + 2) = h23;
    *(uint32_t*)(dL + base) = l01;
    *(uint32_t*)(dL + base + 2) = l23;
}

// ---------------- mean split: a[:,0:256) = split((agg+h)/(deg+1)) ----------------
__global__ void mean_split(const float* __restrict__ agg, const float* __restrict__ h,
                           const float* __restrict__ deg,
                           __nv_bfloat16* __restrict__ aH, __nv_bfloat16* __restrict__ aL) {
    int i = blockIdx.x * blockDim.x + threadIdx.x;   // float4 index
    if (i >= NN * 64) return;
    int row = i >> 6;
    int c = (i & 63) * 4;                            // col in [0,256)
    float inv = 1.0f / (__ldg(deg + row) + 1.0f);
    float4 a = ((const float4*)agg)[i];
    float4 hv = ((const float4*)h)[i];
    float v0 = (a.x + hv.x) * inv, v1 = (a.y + hv.y) * inv;
    float v2 = (a.z + hv.z) * inv, v3 = (a.w + hv.w) * inv;
    uint32_t h01, l01, h23, l23;
    split2(v0, v1, h01, l01);
    split2(v2, v3, h23, l23);
    size_t base = (size_t)(c >> 6) * ((size_t)NNP * 64) + (size_t)row * 64 + swcol(row, c & 63);
    *(uint32_t*)(aH + base) = h01;
    *(uint32_t*)(aH + base + 2) = h23;
    *(uint32_t*)(aL + base) = l01;
    *(uint32_t*)(aL + base + 2) = l23;
}

// ---------------- bf16 tensor GEMM, bulk-copy pipelined ----------------
// C[M,256] = act(A @ W^T + bias); A,W in hi/lo chunk-major swizzled planes.
// CTA 128x256, 512 thr (warp 4Mx4N, 32x64), KC=64, 2-stage bulk double buffer.
#define A_PL   16384            // 128 rows * 128B
#define B_PL   32768            // 256 rows * 128B
#define STG    (2 * A_PL + 2 * B_PL)   // 98304
#define GEMM_SMEM (1024 + 2 * STG)

__global__ __launch_bounds__(512, 1)
void gemm_bf16(const __nv_bfloat16* __restrict__ AH, const __nv_bfloat16* __restrict__ AL,
               int rowsA, int K,
               const __nv_bfloat16* __restrict__ WH, const __nv_bfloat16* __restrict__ WL,
               const float* __restrict__ bias, float* __restrict__ C, int M, int doRelu,
               __nv_bfloat16* outH, __nv_bfloat16* outL, int outColOff) {
    extern __shared__ char smem[];
    const uint32_t sbase = smem_u32(smem);
    const uint32_t bar[2] = {sbase, sbase + 8};
    const uint32_t stg0 = sbase + 1024;

    const int tid = threadIdx.x;
    const int lane = tid & 31;
    const int wid = tid >> 5;
    const int wm = wid & 3;
    const int wn = wid >> 2;
    const int m0w = wm * 32;
    const int n0w = wn * 64;
    const int row0 = blockIdx.x * 128;
    const int nch = K >> 6;

    if (tid == 0) {
        mbar_init(bar[0], 1);
        mbar_init(bar[1], 1);
        asm volatile("fence.proxy.async.shared::cta;" ::: "memory");
    }
    __syncthreads();

    auto issue = [&](int c) {
        uint32_t sb = stg0 + (c & 1) * STG;
        mbar_expect_tx(bar[c & 1], STG);
        const __nv_bfloat16* a0 = AH + ((size_t)c * rowsA + row0) * 64;
        const __nv_bfloat16* a1 = AL + ((size_t)c * rowsA + row0) * 64;
        const __nv_bfloat16* b0 = WH + (size_t)c * (256 * 64);
        const __nv_bfloat16* b1 = WL + (size_t)c * (256 * 64);
        bulk_g2s(sb,                a0, A_PL, bar[c & 1]);
        bulk_g2s(sb + A_PL,         a1, A_PL, bar[c & 1]);
        bulk_g2s(sb + 2 * A_PL,     b0, B_PL, bar[c & 1]);
        bulk_g2s(sb + 2 * A_PL + B_PL, b1, B_PL, bar[c & 1]);
    };

    if (tid == 0) {
        issue(0);
        if (nch > 1) issue(1);
    }

    float acc[2][8][4];
#pragma unroll
    for (int t = 0; t < 2; ++t)
#pragma unroll
        for (int n = 0; n < 8; ++n)
#pragma unroll
            for (int j = 0; j < 4; ++j) acc[t][n][j] = 0.0f;

    // ldmatrix lane constants (proven R5 mapping)
    const int rowA = m0w + (lane & 15);
    const int hiA = lane >> 4;
    const int xa = rowA & 7;
    const uint32_t aBase = (uint32_t)rowA * 128;
    const int nb = (lane < 16) ? (lane & 7) : 8 + (lane & 7);
    const int rowB = n0w + nb;
    const int hiB = (lane >> 3) & 1;
    const int xb = rowB & 7;
    const uint32_t bBase = (uint32_t)rowB * 128;

    int ph[2] = {0, 0};
    for (int c = 0; c < nch; ++c) {
        const int s = c & 1;
        mbar_wait(bar[s], ph[s]);
        ph[s] ^= 1;
        uint32_t sb = stg0 + s * STG;
#pragma unroll
        for (int p = 0; p < 3; ++p) {
            uint32_t Ab = sb + (p == 2 ? A_PL : 0);
            uint32_t Bb = sb + 2 * A_PL + (p == 1 ? B_PL : 0);
#pragma unroll
            for (int ks = 0; ks < 4; ++ks) {
                uint32_t sa = (uint32_t)(((2 * ks + hiA) ^ xa) << 4);
                uint32_t sbb = (uint32_t)(((2 * ks + hiB) ^ xb) << 4);
                uint32_t a[2][4];
#pragma unroll
                for (int t = 0; t < 2; ++t) {
                    uint32_t addr = Ab + aBase + (uint32_t)(t * 2048) + sa;
                    LDSM_X4(a[t][0], a[t][1], a[t][2], a[t][3], addr);
                }
#pragma unroll
                for (int pr = 0; pr < 4; ++pr) {
                    uint32_t baddr = Bb + bBase + (uint32_t)(pr * 2048) + sbb;
                    uint32_t b0, b1, b2, b3;
                    LDSM_X4(b0, b1, b2, b3, baddr);
#pragma unroll
                    for (int t = 0; t < 2; ++t) {
                        mma_bf16(acc[t][pr * 2 + 0], a[t], b0, b1);
                        mma_bf16(acc[t][pr * 2 + 1], a[t], b2, b3);
                    }
                }
            }
        }
        __syncthreads();
        if (c + 2 < nch && tid == 0) issue(c + 2);
    }

    // ---- epilogue ----
#pragma unroll
    for (int t = 0; t < 2; ++t) {
        int row = row0 + m0w + t * 16 + (lane >> 2);
#pragma unroll
        for (int nt = 0; nt < 8; ++nt) {
            int col = n0w + nt * 8 + (lane & 3) * 2;
            float2 bb = __ldg((const float2*)(bias + col));
            float v0 = acc[t][nt][0] + bb.x;
            float v1 = acc[t][nt][1] + bb.y;
            float v2 = acc[t][nt][2] + bb.x;
            float v3 = acc[t][nt][3] + bb.y;
            if (doRelu) {
                v0 = fmaxf(v0, 0.f); v1 = fmaxf(v1, 0.f);
                v2 = fmaxf(v2, 0.f); v3 = fmaxf(v3, 0.f);
            }
            if (row < M) {
                float2 o; o.x = v0; o.y = v1;
                *(float2*)(C + (size_t)row * HID + col) = o;
                if (outH) {
                    uint32_t h01, l01;
                    split2(v0, v1, h01, l01);
                    int gc = outColOff + col;
                    size_t ob = (size_t)(gc >> 6) * ((size_t)NNP * 64) +
                                (size_t)row * 64 + swcol(row, gc & 63);
                    *(uint32_t*)(outH + ob) = h01;
                    *(uint32_t*)(outL + ob) = l01;
                }
            }
            if (row + 8 < M) {
                float2 o; o.x = v2; o.y = v3;
                *(float2*)(C + (size_t)(row + 8) * HID + col) = o;
                if (outH) {
                    uint32_t h23, l23;
                    split2(v2, v3, h23, l23);
                    int gc = outColOff + col;
                    size_t ob = (size_t)(gc >> 6) * ((size_t)NNP * 64) +
                                (size_t)(row + 8) * 64 + swcol(row + 8, gc & 63);
                    *(uint32_t*)(outH + ob) = h23;
                    *(uint32_t*)(outL + ob) = l23;
                }
            }
        }
    }
}

// ---------------- link feature gather -> chunk-major swizzled planes ----------------
__global__ void gather_split(const void* __restrict__ srcI,
                             const void* __restrict__ dstI,
                             const float* __restrict__ h2,
                             __nv_bfloat16* __restrict__ cH,
                             __nv_bfloat16* __restrict__ cL) {
    int t = blockIdx.x * blockDim.x + threadIdx.x;   // one per (link, col-pair)
    if (t >= NL * 128) return;
    int l = t >> 7;
    int k = (t & 127) * 2;                           // k, k+1 in [0,256)
    long long s_n = getIdx(srcI, l);
    long long d_n = getIdx(dstI, l);
    float2 s = *(const float2*)(h2 + s_n * HID + k);
    float2 d = *(const float2*)(h2 + d_n * HID + k);
    float fx[4] = {s.x, d.x, s.x * d.x, fabsf(s.x - d.x)};
    float fy[4] = {s.y, d.y, s.y * d.y, fabsf(s.y - d.y)};
#pragma unroll
    for (int j = 0; j < 4; ++j) {
        int gc = j * 256 + k;
        size_t idx = (size_t)(gc >> 6) * ((size_t)NL * 64) + (size_t)l * 64 + swcol(l, gc & 63);
        uint32_t hi, lo;
        split2(fx[j], fy[j], hi, lo);
        *(uint32_t*)(cH + idx) = hi;
        *(uint32_t*)(cL + idx) = lo;
    }
}

// ---------------- final: sigmoid(hidden . wp2 + b), warp per link ----------------
__global__ void final_kernel(const float* __restrict__ hid,
                             const float* __restrict__ wp2,
                             const float* __restrict__ bp2,
                             float* __restrict__ out) {
    int gtid = blockIdx.x * blockDim.x + threadIdx.x;
    int w = gtid >> 5;
    int lane = gtid & 31;
    if (w >= NL) return;
    const float* h = hid + (long long)w * HID;
    float s = 0.f;
#pragma unroll
    for (int j = 0; j < HID / 32; ++j) {
        int c = lane + j * 32;
        s = fmaf(h[c], wp2[c], s);
    }
#pragma unroll
    for (int o = 16; o > 0; o >>= 1)
        s += __shfl_down_sync(0xffffffffu, s, o);
    if (lane == 0) {
        float logit = s + bp2[0];
        out[w] = 1.0f / (1.0f + expf(-logit));
    }
}

// ---------------- launcher ----------------
extern "C" void kernel_launch(void* const* d_in, const int* in_sizes, int n_in,
                              void* d_out, int out_size) {
    const float* x     = (const float*)d_in[0];
    const void*  ei    = d_in[1];
    const void*  srcI  = d_in[3];
    const void*  dstI  = d_in[4];
    const float* w_emb = (const float*)d_in[5];
    const float* b_emb = (const float*)d_in[6];
    const float* wl0   = (const float*)d_in[8];
    const float* bl0   = (const float*)d_in[9];
    const float* wr0   = (const float*)d_in[10];
    const float* wl1   = (const float*)d_in[13];
    const float* bl1   = (const float*)d_in[14];
    const float* wr1   = (const float*)d_in[15];
    const float* wp1   = (const float*)d_in[18];
    const float* bp1   = (const float*)d_in[19];
    const float* wp2   = (const float*)d_in[20];
    const float* bp2   = (const float*)d_in[21];
    float* out = (float*)d_out;

    float *h0, *h1, *agg, *deg, *hid;
    __nv_bfloat16 *aH, *aL, *xH, *xL, *cH, *cL;
    __nv_bfloat16 *weH, *weL, *w0H, *w0L, *w1H, *w1L, *wpH, *wpL;
    cudaGetSymbolAddress((void**)&h0,  g_h0);
    cudaGetSymbolAddress((void**)&h1,  g_h1);
    cudaGetSymbolAddress((void**)&agg, g_agg);
    cudaGetSymbolAddress((void**)&deg, g_deg);
    cudaGetSymbolAddress((void**)&hid, g_hid);
    cudaGetSymbolAddress((void**)&aH,  g_aH);
    cudaGetSymbolAddress((void**)&aL,  g_aL);
    cudaGetSymbolAddress((void**)&xH,  g_xH);
    cudaGetSymbolAddress((void**)&xL,  g_xL);
    cudaGetSymbolAddress((void**)&cH,  g_cH);
    cudaGetSymbolAddress((void**)&cL,  g_cL);
    cudaGetSymbolAddress((void**)&weH, g_weH);
    cudaGetSymbolAddress((void**)&weL, g_weL);
    cudaGetSymbolAddress((void**)&w0H, g_w0H);
    cudaGetSymbolAddress((void**)&w0L, g_w0L);
    cudaGetSymbolAddress((void**)&w1H, g_w1H);
    cudaGetSymbolAddress((void**)&w1L, g_w1L);
    cudaGetSymbolAddress((void**)&wpH, g_wpH);
    cudaGetSymbolAddress((void**)&wpL, g_wpL);

    cudaFuncSetAttribute(gemm_bf16, cudaFuncAttributeMaxDynamicSharedMemorySize, GEMM_SMEM);

    dim3 gridN((NN + 127) / 128);
    dim3 gridL(NL / 128);

    // Launch order arranged so launch #6 (ncu -s 5 -c 1) is a gemm_bf16.
    detect_kernel<<<1, 256>>>((const int*)ei);                               // 1
    zero_kernel<<<(NN + 255) / 256, 256>>>(deg, NN);                         // 2
    zero_kernel<<<2048, 256>>>(agg, NN * HID);                               // 3
    pack_w<<<(256 * 128 + 255) / 256, 256>>>(w_emb, weH, weL, 128, 0);       // 4
    split_x<<<(NN * 32 + 255) / 256, 256>>>(x, xH, xL);                      // 5
    // 6: embedding GEMM (captured by ncu)
    gemm_bf16<<<gridN, 512, GEMM_SMEM>>>(xH, xL, NNP, 128, weH, weL,
                                         b_emb, h0, NN, 0, aH, aL, 256);

    deg_kernel<<<(NE + 255) / 256, 256>>>(ei, deg);
    pack_w<<<(256 * 256 + 255) / 256, 256>>>(wl0, w0H, w0L, 256, 0);
    pack_w<<<(256 * 256 + 255) / 256, 256>>>(wr0, w0H, w0L, 256, 256);
    pack_w<<<(256 * 256 + 255) / 256, 256>>>(wl1, w1H, w1L, 256, 0);
    pack_w<<<(256 * 256 + 255) / 256, 256>>>(wr1, w1H, w1L, 256, 256);
    pack_w<<<(256 * 1024 + 255) / 256, 256>>>(wp1, wpH, wpL, 1024, 0);

    // layer 0
    scatter_kernel<<<(NE * 32 + 255) / 256, 256>>>(ei, h0, agg);
    mean_split<<<(NN * 64 + 255) / 256, 256>>>(agg, h0, deg, aH, aL);
    gemm_bf16<<<gridN, 512, GEMM_SMEM>>>(aH, aL, NNP, 512, w0H, w0L,
                                         bl0, h1, NN, 1, aH, aL, 256);

    // layer 1 (h2 into h0 buffer)
    zero_kernel<<<2048, 256>>>(agg, NN * HID);
    scatter_kernel<<<(NE * 32 + 255) / 256, 256>>>(ei, h1, agg);
    mean_split<<<(NN * 64 + 255) / 256, 256>>>(agg, h1, deg, aH, aL);
    gemm_bf16<<<gridN, 512, GEMM_SMEM>>>(aH, aL, NNP, 512, w1H, w1L,
                                         bl1, h0, NN, 1, nullptr, nullptr, 0);

    // link head
    gather_split<<<(NL * 128 + 255) / 256, 256>>>(srcI, dstI, h0, cH, cL);
    gemm_bf16<<<gridL, 512, GEMM_SMEM>>>(cH, cL, NL, 1024, wpH, wpL,
                                         bp1, hid, NL, 1, nullptr, nullptr, 0);
    final_kernel<<<(NL * 32 + 255) / 256, 256>>>(hid, wp2, bp2, out);
}